// round 9
// baseline (speedup 1.0000x reference)
#include <cuda_runtime.h>
#include <cstdint>

#define N_NODES 100000
#define N_EDGES 1600000
#define D_IN    128
#define D_OUT   64

// Scratch: h = x @ W   (100000 x 64 fp32 = 25.6 MB, L2-resident)
__device__ __align__(256) float g_h[N_NODES * D_OUT];

// Index-width flag: 1 = indices are int64, 0 = int32
__device__ int g_idx64;

// ---------------------------------------------------------------------------
// helpers
// ---------------------------------------------------------------------------
__device__ __forceinline__ uint32_t bf16x2_pack(float hi, float lo) {
    uint32_t r;   // r[31:16] = cvt(hi), r[15:0] = cvt(lo)
    asm("cvt.rn.bf16x2.f32 %0, %1, %2;" : "=r"(r) : "f"(hi), "f"(lo));
    return r;
}
__device__ __forceinline__ float bfu_lo(uint32_t p) {   // expand low bf16
    return __uint_as_float(p << 16);
}
__device__ __forceinline__ float bfu_hi(uint32_t p) {   // expand high bf16
    return __uint_as_float(p & 0xffff0000u);
}
__device__ __forceinline__ void mma_bf16(float* c, const uint32_t* a,
                                         uint32_t b0, uint32_t b1) {
    asm("mma.sync.aligned.m16n8k16.row.col.f32.bf16.bf16.f32 "
        "{%0,%1,%2,%3}, {%4,%5,%6,%7}, {%8,%9}, {%0,%1,%2,%3};"
        : "+f"(c[0]), "+f"(c[1]), "+f"(c[2]), "+f"(c[3])
        : "r"(a[0]), "r"(a[1]), "r"(a[2]), "r"(a[3]), "r"(b0), "r"(b1));
}

// ---------------------------------------------------------------------------
// Kernel 1: h = x @ W via mma.sync bf16 3-term split.
// m = nodes (16), n = output cols (8), k = D_IN chunked by 16.
// A = x streamed from global (row-major frags = contiguous float2 pairs);
// B = W column-slice held in registers (hi+lo, 32 regs), precomputed once.
// Block 256 = 8 warps = 8 col-groups covering all 64 cols of one 16-node
// tile; 625 blocks x 10 tiles = 100000 nodes exactly.
// ---------------------------------------------------------------------------
#define GEMM_BLOCKS 625
#define TILES_PER_BLOCK 10

__global__ void __launch_bounds__(256) gemm_mma_kernel(
    const float* __restrict__ x, const float* __restrict__ W,
    const void* __restrict__ src) {

    if (blockIdx.x == 0 && threadIdx.x == 0) {
        // int32 data read as u64 packs two indices -> top bits nonzero w.h.p.
        const unsigned long long* p = (const unsigned long long*)src;
        int is64 = 1;
        for (int i = 0; i < 8; i++)
            if (p[i] >= (unsigned long long)N_NODES) is64 = 0;
        g_idx64 = is64;
    }

    const int warp = threadIdx.x >> 5;   // = col-group 0..7
    const int lane = threadIdx.x & 31;
    const int tig  = lane & 3;
    const int grp  = lane >> 2;
    const int col0 = warp * 8;

    // ---- Precompute B fragments (col-major k x n): B[k][n] = W[k][col0+n].
    // b0: n=grp, k=2tig,2tig+1 ; b1: n=grp, k=2tig+8,+9  (low half = even k)
    uint32_t Bh[8][2], Bl[8][2];
#pragma unroll
    for (int ks = 0; ks < 8; ks++) {
#pragma unroll
        for (int r = 0; r < 2; r++) {
            const int k = ks * 16 + 2 * tig + (r ? 8 : 0);
            const float w0 = __ldg(W + (size_t)k * D_OUT + col0 + grp);
            const float w1 = __ldg(W + (size_t)(k + 1) * D_OUT + col0 + grp);
            const uint32_t hi = bf16x2_pack(w1, w0);
            Bh[ks][r] = hi;
            Bl[ks][r] = bf16x2_pack(w1 - bfu_hi(hi), w0 - bfu_lo(hi));
        }
    }

    for (int it = 0; it < TILES_PER_BLOCK; it++) {
        const int node0 = (blockIdx.x * TILES_PER_BLOCK + it) * 16;
        const float* xr0 = x + (size_t)(node0 + grp) * D_IN;       // row grp
        const float* xr1 = x + (size_t)(node0 + grp + 8) * D_IN;   // row grp+8

        float c[4] = {0.f, 0.f, 0.f, 0.f};

#pragma unroll
        for (int ks = 0; ks < 8; ks++) {
            // A frags (row-major m x k): a0 row grp k2tig | a1 row grp+8 |
            //                            a2 row grp k+8   | a3 row grp+8 k+8
            const float2 p0 = *(const float2*)(xr0 + ks * 16 + 2 * tig);
            const float2 p1 = *(const float2*)(xr1 + ks * 16 + 2 * tig);
            const float2 p2 = *(const float2*)(xr0 + ks * 16 + 8 + 2 * tig);
            const float2 p3 = *(const float2*)(xr1 + ks * 16 + 8 + 2 * tig);

            uint32_t ah[4], al[4];
            ah[0] = bf16x2_pack(p0.y, p0.x);
            ah[1] = bf16x2_pack(p1.y, p1.x);
            ah[2] = bf16x2_pack(p2.y, p2.x);
            ah[3] = bf16x2_pack(p3.y, p3.x);
            al[0] = bf16x2_pack(p0.y - bfu_hi(ah[0]), p0.x - bfu_lo(ah[0]));
            al[1] = bf16x2_pack(p1.y - bfu_hi(ah[1]), p1.x - bfu_lo(ah[1]));
            al[2] = bf16x2_pack(p2.y - bfu_hi(ah[2]), p2.x - bfu_lo(ah[2]));
            al[3] = bf16x2_pack(p3.y - bfu_hi(ah[3]), p3.x - bfu_lo(ah[3]));

            mma_bf16(c, ah, Bh[ks][0], Bh[ks][1]);   // xh * Wh
            mma_bf16(c, al, Bh[ks][0], Bh[ks][1]);   // xl * Wh
            mma_bf16(c, ah, Bl[ks][0], Bl[ks][1]);   // xh * Wl
        }

        // C: c0,c1 = (row grp,   cols 2tig,2tig+1)
        //    c2,c3 = (row grp+8, cols 2tig,2tig+1)   -> contiguous float2
        *(float2*)&g_h[(size_t)(node0 + grp)     * D_OUT + col0 + 2 * tig] =
            make_float2(c[0], c[1]);
        *(float2*)&g_h[(size_t)(node0 + grp + 8) * D_OUT + col0 + 2 * tig] =
            make_float2(c[2], c[3]);
    }
}

// ---------------------------------------------------------------------------
// Kernel 2: scatter.  out[src] += w * h[dst].  16 lanes per edge, 8 edges
// per thread, batched index loads then independent gather->red chains.
// ---------------------------------------------------------------------------
__global__ void __launch_bounds__(256) scatter_kernel(
    const float* __restrict__ ew,
    const void* __restrict__ srcp,
    const void* __restrict__ dstp,
    float* __restrict__ out) {

    const int t  = blockIdx.x * 256 + threadIdx.x;   // 3.2M threads, exact
    const int c  = t & 15;
    const int g  = t >> 4;
    const int e0 = 8 * g;

    const int idx64 = g_idx64;
    const int* sp = (const int*)srcp;
    const int* dp = (const int*)dstp;

    int s[8], d[8];
    float w[8];
#pragma unroll
    for (int i = 0; i < 8; i++) {
        const int e = e0 + i;
        if (idx64) {                 // little-endian low words of int64
            s[i] = __ldg(sp + 2 * e);
            d[i] = __ldg(dp + 2 * e);
        } else {
            s[i] = __ldg(sp + e);
            d[i] = __ldg(dp + e);
        }
        w[i] = __ldg(ew + e);
    }

    float4 v[8];
#pragma unroll
    for (int i = 0; i < 8; i++)
        v[i] = __ldg((const float4*)(g_h + (size_t)d[i] * D_OUT) + c);

#pragma unroll
    for (int i = 0; i < 8; i++) {
        if ((unsigned)s[i] < N_NODES) {
            float* p = out + (size_t)s[i] * D_OUT + 4 * c;
            asm volatile("red.global.add.v4.f32 [%0], {%1, %2, %3, %4};"
                         :: "l"(p), "f"(v[i].x * w[i]), "f"(v[i].y * w[i]),
                            "f"(v[i].z * w[i]), "f"(v[i].w * w[i]) : "memory");
        }
    }
}

// ---------------------------------------------------------------------------
// Kernel 3: in-place ReLU, 2 float4 per thread
// ---------------------------------------------------------------------------
#define RELU_HALF (N_NODES * D_OUT / 4 / 2)   // 800000 float4 per half

__global__ void __launch_bounds__(256) relu_kernel(float4* __restrict__ out) {
    const int i = blockIdx.x * 256 + threadIdx.x;
    float4 a = out[i];
    float4 b = out[i + RELU_HALF];
    a.x = fmaxf(a.x, 0.f); a.y = fmaxf(a.y, 0.f);
    a.z = fmaxf(a.z, 0.f); a.w = fmaxf(a.w, 0.f);
    b.x = fmaxf(b.x, 0.f); b.y = fmaxf(b.y, 0.f);
    b.z = fmaxf(b.z, 0.f); b.w = fmaxf(b.w, 0.f);
    out[i] = a;
    out[i + RELU_HALF] = b;
}

// ---------------------------------------------------------------------------
extern "C" void kernel_launch(void* const* d_in, const int* in_sizes, int n_in,
                              void* d_out, int out_size) {
    const float* x   = (const float*)d_in[0];      // [100000, 128]
    const float* ew  = (const float*)d_in[1];      // [1600000]
    const float* W   = (const float*)d_in[2];      // [128, 64]
    const void*  src = d_in[3];                    // [1600000] int64/int32
    const void*  dst = d_in[4];                    // [1600000] int64/int32
    float* out = (float*)d_out;                    // [100000, 64]

    // zero the poisoned output (graph-capturable, no alloc)
    cudaMemsetAsync(out, 0, (size_t)N_NODES * D_OUT * sizeof(float));

    // h = x @ W on mma.sync bf16x3: 625 blocks x 256
    gemm_mma_kernel<<<GEMM_BLOCKS, 256>>>(x, W, src);

    // scatter: E/8 groups * 16 lanes = 3.2M threads -> 12500 blocks
    scatter_kernel<<<(N_EDGES * 2) / 256, 256>>>(ew, src, dst, out);

    // ReLU: 800000 threads -> 3125 blocks
    relu_kernel<<<RELU_HALF / 256, 256>>>((float4*)out);
}

// round 11
// speedup vs baseline: 1.0745x; 1.0745x over previous
#include <cuda_runtime.h>
#include <cuda_fp16.h>
#include <cstdint>

#define N_NODES 100000
#define N_EDGES 1600000
#define D_IN    128
#define D_OUT   64

// Scratch: h = x @ W in fp16 (100000 x 64 halves = 12.8 MB, L2-resident).
// Stored as packed half2 words: 32 uint32 per row.
__device__ __align__(256) uint32_t g_h16[N_NODES * 32];

// Index-width flag: 1 = indices are int64, 0 = int32
__device__ int g_idx64;

__device__ __forceinline__ uint32_t f2h2(float a, float b) {   // low=a, high=b
    const __half2 h = __floats2half2_rn(a, b);
    return *(const uint32_t*)&h;
}

// ---------------------------------------------------------------------------
// Kernel 1: h = x @ W  (+ index-width probe in block 0).
// 128 threads, block tile 128 rows x 64 cols, thread tile 8 rows x 8 cols.
// K chunked by 32 through smem.  fma.rn.f32x2 inner product; fp16 output.
// ---------------------------------------------------------------------------
__global__ void __launch_bounds__(128) gemm_kernel(const float* __restrict__ x,
                                                   const float* __restrict__ W,
                                                   const void* __restrict__ src) {
    __shared__ float Ws[D_IN * D_OUT];   // 32 KB, [k][col]
    __shared__ float Xs[128 * 32];       // 16 KB, [row][k-local]

    const int tid = threadIdx.x;

    if (blockIdx.x == 0 && tid == 0) {
        // int32 data read as u64 packs two indices -> top bits nonzero w.h.p.
        const unsigned long long* p = (const unsigned long long*)src;
        int is64 = 1;
        for (int i = 0; i < 8; i++)
            if (p[i] >= (unsigned long long)N_NODES) is64 = 0;
        g_idx64 = is64;
    }

    // Load all of W: 2048 float4, 16 per thread
    {
        const float4* Wg  = (const float4*)W;
        float4*       Wsv = (float4*)Ws;
#pragma unroll
        for (int i = 0; i < 16; i++) Wsv[tid + i * 128] = Wg[tid + i * 128];
    }

    const int row0 = blockIdx.x * 128;
    const int tx = tid & 7;    // cols [8*tx, 8*tx+7]
    const int ty = tid >> 3;   // rows [8*ty, 8*ty+7] (local)

    unsigned long long acc[8][4];
#pragma unroll
    for (int r = 0; r < 8; r++)
#pragma unroll
        for (int c = 0; c < 4; c++) acc[r][c] = 0ull;

    for (int k0 = 0; k0 < D_IN; k0 += 32) {
        __syncthreads();   // protect Xs from previous chunk's readers
        // Load X chunk [128 rows x 32 k]: 1024 float4, 8 per thread, coalesced
#pragma unroll
        for (int i = 0; i < 8; i++) {
            const int lin  = tid + i * 128;
            const int row  = lin >> 3;
            const int slot = lin & 7;
            int grow = row0 + row;
            if (grow >= N_NODES) grow = N_NODES - 1;   // clamp (dup, unused)
            const float4 v =
                __ldg((const float4*)(x + (size_t)grow * D_IN + k0) + slot);
            *(float4*)&Xs[row * 32 + slot * 4] = v;
        }
        __syncthreads();

#pragma unroll
        for (int kk = 0; kk < 32; kk += 4) {
            float4 xv[8];
#pragma unroll
            for (int r = 0; r < 8; r++)
                xv[r] = *(const float4*)&Xs[(ty * 8 + r) * 32 + kk];

#pragma unroll
            for (int j = 0; j < 4; j++) {
                const ulonglong2 wvA =
                    *(const ulonglong2*)&Ws[(k0 + kk + j) * D_OUT + 8 * tx];
                const ulonglong2 wvB =
                    *(const ulonglong2*)&Ws[(k0 + kk + j) * D_OUT + 8 * tx + 4];
#pragma unroll
                for (int r = 0; r < 8; r++) {
                    const float xs = (j == 0) ? xv[r].x : (j == 1) ? xv[r].y
                                   : (j == 2) ? xv[r].z : xv[r].w;
                    unsigned long long d;
                    asm("mov.b64 %0, {%1, %1};" : "=l"(d) : "f"(xs));
                    asm("fma.rn.f32x2 %0, %1, %2, %0;" : "+l"(acc[r][0]) : "l"(d), "l"(wvA.x));
                    asm("fma.rn.f32x2 %0, %1, %2, %0;" : "+l"(acc[r][1]) : "l"(d), "l"(wvA.y));
                    asm("fma.rn.f32x2 %0, %1, %2, %0;" : "+l"(acc[r][2]) : "l"(d), "l"(wvB.x));
                    asm("fma.rn.f32x2 %0, %1, %2, %0;" : "+l"(acc[r][3]) : "l"(d), "l"(wvB.y));
                }
            }
        }
    }

    // Store 8 rows x 8 cols as packed fp16 (one uint4 = 8 halves per row).
    // Col 8*tx -> half index 8*tx -> word index 4*tx (16B-aligned).
#pragma unroll
    for (int r = 0; r < 8; r++) {
        const int row = row0 + ty * 8 + r;
        if (row < N_NODES) {
            float4 lo, hi;
            asm("mov.b64 {%0, %1}, %2;" : "=f"(lo.x), "=f"(lo.y) : "l"(acc[r][0]));
            asm("mov.b64 {%0, %1}, %2;" : "=f"(lo.z), "=f"(lo.w) : "l"(acc[r][1]));
            asm("mov.b64 {%0, %1}, %2;" : "=f"(hi.x), "=f"(hi.y) : "l"(acc[r][2]));
            asm("mov.b64 {%0, %1}, %2;" : "=f"(hi.z), "=f"(hi.w) : "l"(acc[r][3]));
            uint4 pk;
            pk.x = f2h2(lo.x, lo.y);
            pk.y = f2h2(lo.z, lo.w);
            pk.z = f2h2(hi.x, hi.y);
            pk.w = f2h2(hi.z, hi.w);
            *(uint4*)&g_h16[(size_t)row * 32 + 4 * tx] = pk;
        }
    }
}

// ---------------------------------------------------------------------------
// Kernel 2: scatter.  out[src] += w * h[dst].  8 lanes per edge (one uint4 =
// 8 fp16 each), 8 edges per thread: batched index loads, then 8 independent
// gather chains; each lane issues two red.v4.f32.
// ---------------------------------------------------------------------------
__global__ void __launch_bounds__(256) scatter_kernel(
    const float* __restrict__ ew,
    const void* __restrict__ srcp,
    const void* __restrict__ dstp,
    float* __restrict__ out) {

    const int t  = blockIdx.x * 256 + threadIdx.x;   // 1.6M threads, exact
    const int c  = t & 7;                            // uint4 slot in fp16 row
    const int g  = t >> 3;                           // edge octet
    const int e0 = 8 * g;

    const int idx64 = g_idx64;
    const int* sp = (const int*)srcp;
    const int* dp = (const int*)dstp;

    int s[8], d[8];
    float w[8];
#pragma unroll
    for (int i = 0; i < 8; i++) {
        const int e = e0 + i;
        if (idx64) {                 // little-endian low words of int64
            s[i] = __ldg(sp + 2 * e);
            d[i] = __ldg(dp + 2 * e);
        } else {
            s[i] = __ldg(sp + e);
            d[i] = __ldg(dp + e);
        }
        w[i] = __ldg(ew + e);
    }

    uint4 v[8];
#pragma unroll
    for (int i = 0; i < 8; i++)
        v[i] = __ldg((const uint4*)(g_h16 + (size_t)d[i] * 32) + c);

#pragma unroll
    for (int i = 0; i < 8; i++) {
        if ((unsigned)s[i] < N_NODES) {
            const __half2* hv = (const __half2*)&v[i];
            const float2 f0 = __half22float2(hv[0]);
            const float2 f1 = __half22float2(hv[1]);
            const float2 f2 = __half22float2(hv[2]);
            const float2 f3 = __half22float2(hv[3]);
            float* p = out + (size_t)s[i] * D_OUT + 8 * c;
            asm volatile("red.global.add.v4.f32 [%0], {%1, %2, %3, %4};"
                         :: "l"(p), "f"(f0.x * w[i]), "f"(f0.y * w[i]),
                            "f"(f1.x * w[i]), "f"(f1.y * w[i]) : "memory");
            asm volatile("red.global.add.v4.f32 [%0], {%1, %2, %3, %4};"
                         :: "l"(p + 4), "f"(f2.x * w[i]), "f"(f2.y * w[i]),
                            "f"(f3.x * w[i]), "f"(f3.y * w[i]) : "memory");
        }
    }
}

// ---------------------------------------------------------------------------
// Kernel 3: in-place ReLU, 2 float4 per thread
// ---------------------------------------------------------------------------
#define RELU_HALF (N_NODES * D_OUT / 4 / 2)   // 800000 float4 per half

__global__ void __launch_bounds__(256) relu_kernel(float4* __restrict__ out) {
    const int i = blockIdx.x * 256 + threadIdx.x;
    float4 a = out[i];
    float4 b = out[i + RELU_HALF];
    a.x = fmaxf(a.x, 0.f); a.y = fmaxf(a.y, 0.f);
    a.z = fmaxf(a.z, 0.f); a.w = fmaxf(a.w, 0.f);
    b.x = fmaxf(b.x, 0.f); b.y = fmaxf(b.y, 0.f);
    b.z = fmaxf(b.z, 0.f); b.w = fmaxf(b.w, 0.f);
    out[i] = a;
    out[i + RELU_HALF] = b;
}

// ---------------------------------------------------------------------------
extern "C" void kernel_launch(void* const* d_in, const int* in_sizes, int n_in,
                              void* d_out, int out_size) {
    const float* x   = (const float*)d_in[0];      // [100000, 128]
    const float* ew  = (const float*)d_in[1];      // [1600000]
    const float* W   = (const float*)d_in[2];      // [128, 64]
    const void*  src = d_in[3];                    // [1600000] int64/int32
    const void*  dst = d_in[4];                    // [1600000] int64/int32
    float* out = (float*)d_out;                    // [100000, 64]

    // zero the poisoned output (graph-capturable, no alloc)
    cudaMemsetAsync(out, 0, (size_t)N_NODES * D_OUT * sizeof(float));

    // h = x @ W (+probe): ceil(100000/128) = 782 blocks
    gemm_kernel<<<(N_NODES + 127) / 128, 128>>>(x, W, src);

    // scatter: E * 8 lanes / 8 edges-per-thread = 1.6M threads -> 6250 blocks
    scatter_kernel<<<N_EDGES / 256, 256>>>(ew, src, dst, out);

    // ReLU: 800000 threads -> 3125 blocks
    relu_kernel<<<RELU_HALF / 256, 256>>>((float4*)out);
}

// round 12
// speedup vs baseline: 1.3978x; 1.3009x over previous
#include <cuda_runtime.h>
#include <cuda_fp16.h>
#include <cstdint>

#define N_NODES 100000
#define N_EDGES 1600000
#define D_IN    128
#define D_OUT   64

// Scratch: h = x @ W in fp16 (100000 x 64 halves = 12.8 MB, L2-resident).
// Stored as packed half2 words: 32 uint32 per row.
__device__ __align__(256) uint32_t g_h16[N_NODES * 32];

// Index-width flag: 1 = indices are int64, 0 = int32
__device__ int g_idx64;

__device__ __forceinline__ uint32_t f2h2(float a, float b) {   // low=a, high=b
    const __half2 h = __floats2half2_rn(a, b);
    return *(const uint32_t*)&h;
}

// ---------------------------------------------------------------------------
// Kernel 1: h = x @ W  (+ index-width probe in block 0).
// 128 threads, block tile 128 rows x 64 cols, thread tile 8 rows x 8 cols.
// K chunked by 32 through smem.  fma.rn.f32x2 inner product; fp16 output.
// (Measured 48.4us in R11.)
// ---------------------------------------------------------------------------
__global__ void __launch_bounds__(128) gemm_kernel(const float* __restrict__ x,
                                                   const float* __restrict__ W,
                                                   const void* __restrict__ src) {
    __shared__ float Ws[D_IN * D_OUT];   // 32 KB, [k][col]
    __shared__ float Xs[128 * 32];       // 16 KB, [row][k-local]

    const int tid = threadIdx.x;

    if (blockIdx.x == 0 && tid == 0) {
        // int32 data read as u64 packs two indices -> top bits nonzero w.h.p.
        const unsigned long long* p = (const unsigned long long*)src;
        int is64 = 1;
        for (int i = 0; i < 8; i++)
            if (p[i] >= (unsigned long long)N_NODES) is64 = 0;
        g_idx64 = is64;
    }

    // Load all of W: 2048 float4, 16 per thread
    {
        const float4* Wg  = (const float4*)W;
        float4*       Wsv = (float4*)Ws;
#pragma unroll
        for (int i = 0; i < 16; i++) Wsv[tid + i * 128] = Wg[tid + i * 128];
    }

    const int row0 = blockIdx.x * 128;
    const int tx = tid & 7;    // cols [8*tx, 8*tx+7]
    const int ty = tid >> 3;   // rows [8*ty, 8*ty+7] (local)

    unsigned long long acc[8][4];
#pragma unroll
    for (int r = 0; r < 8; r++)
#pragma unroll
        for (int c = 0; c < 4; c++) acc[r][c] = 0ull;

    for (int k0 = 0; k0 < D_IN; k0 += 32) {
        __syncthreads();   // protect Xs from previous chunk's readers
        // Load X chunk [128 rows x 32 k]: 1024 float4, 8 per thread, coalesced
#pragma unroll
        for (int i = 0; i < 8; i++) {
            const int lin  = tid + i * 128;
            const int row  = lin >> 3;
            const int slot = lin & 7;
            int grow = row0 + row;
            if (grow >= N_NODES) grow = N_NODES - 1;   // clamp (dup, unused)
            const float4 v =
                __ldg((const float4*)(x + (size_t)grow * D_IN + k0) + slot);
            *(float4*)&Xs[row * 32 + slot * 4] = v;
        }
        __syncthreads();

#pragma unroll
        for (int kk = 0; kk < 32; kk += 4) {
            float4 xv[8];
#pragma unroll
            for (int r = 0; r < 8; r++)
                xv[r] = *(const float4*)&Xs[(ty * 8 + r) * 32 + kk];

#pragma unroll
            for (int j = 0; j < 4; j++) {
                const ulonglong2 wvA =
                    *(const ulonglong2*)&Ws[(k0 + kk + j) * D_OUT + 8 * tx];
                const ulonglong2 wvB =
                    *(const ulonglong2*)&Ws[(k0 + kk + j) * D_OUT + 8 * tx + 4];
#pragma unroll
                for (int r = 0; r < 8; r++) {
                    const float xs = (j == 0) ? xv[r].x : (j == 1) ? xv[r].y
                                   : (j == 2) ? xv[r].z : xv[r].w;
                    unsigned long long d;
                    asm("mov.b64 %0, {%1, %1};" : "=l"(d) : "f"(xs));
                    asm("fma.rn.f32x2 %0, %1, %2, %0;" : "+l"(acc[r][0]) : "l"(d), "l"(wvA.x));
                    asm("fma.rn.f32x2 %0, %1, %2, %0;" : "+l"(acc[r][1]) : "l"(d), "l"(wvA.y));
                    asm("fma.rn.f32x2 %0, %1, %2, %0;" : "+l"(acc[r][2]) : "l"(d), "l"(wvB.x));
                    asm("fma.rn.f32x2 %0, %1, %2, %0;" : "+l"(acc[r][3]) : "l"(d), "l"(wvB.y));
                }
            }
        }
    }

    // Store 8 rows x 8 cols as packed fp16 (one uint4 = 8 halves per row).
    // Col 8*tx -> half index 8*tx -> word index 4*tx (16B-aligned).
#pragma unroll
    for (int r = 0; r < 8; r++) {
        const int row = row0 + ty * 8 + r;
        if (row < N_NODES) {
            float4 lo, hi;
            asm("mov.b64 {%0, %1}, %2;" : "=f"(lo.x), "=f"(lo.y) : "l"(acc[r][0]));
            asm("mov.b64 {%0, %1}, %2;" : "=f"(lo.z), "=f"(lo.w) : "l"(acc[r][1]));
            asm("mov.b64 {%0, %1}, %2;" : "=f"(hi.x), "=f"(hi.y) : "l"(acc[r][2]));
            asm("mov.b64 {%0, %1}, %2;" : "=f"(hi.z), "=f"(hi.w) : "l"(acc[r][3]));
            uint4 pk;
            pk.x = f2h2(lo.x, lo.y);
            pk.y = f2h2(lo.z, lo.w);
            pk.z = f2h2(hi.x, hi.y);
            pk.w = f2h2(hi.z, hi.w);
            *(uint4*)&g_h16[(size_t)row * 32 + 4 * tx] = pk;
        }
    }
}

// ---------------------------------------------------------------------------
// Kernel 2: scatter.  out[src] += w * h[dst].  R5 topology: 16 lanes/edge,
// 8 edges/thread, 3.2M threads, ONE red.v4.f32 per lane per edge.  Only the
// gather is fp16 now: lane c loads uint2 (4 halves, 8B).
// ---------------------------------------------------------------------------
__global__ void __launch_bounds__(256) scatter_kernel(
    const float* __restrict__ ew,
    const void* __restrict__ srcp,
    const void* __restrict__ dstp,
    float* __restrict__ out) {

    const int t  = blockIdx.x * 256 + threadIdx.x;   // 3.2M threads, exact
    const int c  = t & 15;                           // 4-half slot in row
    const int g  = t >> 4;                           // edge octet
    const int e0 = 8 * g;

    const int idx64 = g_idx64;
    const int* sp = (const int*)srcp;
    const int* dp = (const int*)dstp;

    int s[8], d[8];
    float w[8];
#pragma unroll
    for (int i = 0; i < 8; i++) {
        const int e = e0 + i;
        if (idx64) {                 // little-endian low words of int64
            s[i] = __ldg(sp + 2 * e);
            d[i] = __ldg(dp + 2 * e);
        } else {
            s[i] = __ldg(sp + e);
            d[i] = __ldg(dp + e);
        }
        w[i] = __ldg(ew + e);
    }

    uint2 v[8];
#pragma unroll
    for (int i = 0; i < 8; i++)
        v[i] = __ldg((const uint2*)(g_h16 + (size_t)d[i] * 32) + c);

#pragma unroll
    for (int i = 0; i < 8; i++) {
        if ((unsigned)s[i] < N_NODES) {
            const float2 f0 = __half22float2(*(const __half2*)&v[i].x);
            const float2 f1 = __half22float2(*(const __half2*)&v[i].y);
            float* p = out + (size_t)s[i] * D_OUT + 4 * c;
            asm volatile("red.global.add.v4.f32 [%0], {%1, %2, %3, %4};"
                         :: "l"(p), "f"(f0.x * w[i]), "f"(f0.y * w[i]),
                            "f"(f1.x * w[i]), "f"(f1.y * w[i]) : "memory");
        }
    }
}

// ---------------------------------------------------------------------------
// Kernel 3: in-place ReLU, 2 float4 per thread
// ---------------------------------------------------------------------------
#define RELU_HALF (N_NODES * D_OUT / 4 / 2)   // 800000 float4 per half

__global__ void __launch_bounds__(256) relu_kernel(float4* __restrict__ out) {
    const int i = blockIdx.x * 256 + threadIdx.x;
    float4 a = out[i];
    float4 b = out[i + RELU_HALF];
    a.x = fmaxf(a.x, 0.f); a.y = fmaxf(a.y, 0.f);
    a.z = fmaxf(a.z, 0.f); a.w = fmaxf(a.w, 0.f);
    b.x = fmaxf(b.x, 0.f); b.y = fmaxf(b.y, 0.f);
    b.z = fmaxf(b.z, 0.f); b.w = fmaxf(b.w, 0.f);
    out[i] = a;
    out[i + RELU_HALF] = b;
}

// ---------------------------------------------------------------------------
extern "C" void kernel_launch(void* const* d_in, const int* in_sizes, int n_in,
                              void* d_out, int out_size) {
    const float* x   = (const float*)d_in[0];      // [100000, 128]
    const float* ew  = (const float*)d_in[1];      // [1600000]
    const float* W   = (const float*)d_in[2];      // [128, 64]
    const void*  src = d_in[3];                    // [1600000] int64/int32
    const void*  dst = d_in[4];                    // [1600000] int64/int32
    float* out = (float*)d_out;                    // [100000, 64]

    // zero the poisoned output (graph-capturable, no alloc)
    cudaMemsetAsync(out, 0, (size_t)N_NODES * D_OUT * sizeof(float));

    // h = x @ W (+probe): ceil(100000/128) = 782 blocks
    gemm_kernel<<<(N_NODES + 127) / 128, 128>>>(x, W, src);

    // scatter: E/8 octets * 16 lanes = 3.2M threads -> 12500 blocks
    scatter_kernel<<<(N_EDGES * 2) / 256, 256>>>(ew, src, dst, out);

    // ReLU: 800000 threads -> 3125 blocks
    relu_kernel<<<RELU_HALF / 256, 256>>>((float4*)out);
}